// round 16
// baseline (speedup 1.0000x reference)
#include <cuda_runtime.h>
#include <cuda_fp16.h>
#include <mma.h>
#include <math.h>
#include <stdint.h>

using namespace nvcuda;

constexpr int D = 256;
constexpr int NSTR = 6;
constexpr int NSCA = 20;
constexpr int TK = 4;
constexpr int BATCH = 32768;
constexpr int T_TOK = BATCH * TK;   // 131072
constexpr float LN_EPS = 1e-5f;

// ---------------- device scratch ----------------
__device__ float g_w[TK];
__device__ int   g_ti[TK];
__device__ int   g_tj[TK];

__device__ __align__(16) __half g_crossh[(size_t)T_TOK * D];  // cross_f + cm_b2
__device__ __align__(16) __half g_difh  [(size_t)T_TOK * D];  // diff_f + df_b2

__device__ __align__(16) __half g_hw1[768 * 256];
__device__ __align__(16) __half g_hw2[256 * 256];
__device__ __align__(16) __half g_hw3[512 * 256];
__device__ __align__(16) __half g_hw4[256 * 256];
__device__ __align__(16) __half g_hw5[768 * 512];
__device__ __align__(16) __half g_hw6[512 * 256];

// ---------------- prep: top-k + softmax ----------------
__global__ void prep_kernel(const float* __restrict__ scores,
                            const float* __restrict__ tempp) {
  if (threadIdx.x != 0) return;
  const int NTOT = NSTR * NSCA;
  bool used[NSTR * NSCA] = {};
  float vals[TK]; int idx[TK];
  for (int r = 0; r < TK; r++) {
    float best = -INFINITY; int bi = 0;
    for (int i = 0; i < NTOT; i++)
      if (!used[i]) { float v = scores[i]; if (v > best) { best = v; bi = i; } }
    used[bi] = true; vals[r] = best; idx[r] = bi;
  }
  float tmp = fmaxf(tempp[0], 0.1f);
  float m = vals[0], e[TK], se = 0.f;
  for (int r = 0; r < TK; r++) { e[r] = expf((vals[r] - m) / tmp); se += e[r]; }
  for (int r = 0; r < TK; r++) {
    g_w[r]  = e[r] / se;
    g_ti[r] = idx[r] / NSCA;
    g_tj[r] = idx[r] % NSCA;
  }
}

// ---------------- single-launch fp32->fp16 weight conversion ----------------
struct CvtArgs {
  const float* src[6];
  __half* dst[6];
  int cum[7];
};
__global__ void cvt_all(CvtArgs a) {
  int i = blockIdx.x * blockDim.x + threadIdx.x;
  if (i >= a.cum[6]) return;
  int seg = 0;
  #pragma unroll
  for (int s = 1; s < 6; s++) seg += (i >= a.cum[s]) ? 1 : 0;
  const int j = i - a.cum[seg];
  float4 v = *(const float4*)(a.src[seg] + (size_t)j * 4);
  __half2 p = __floats2half2_rn(v.x, v.y);
  __half2 q = __floats2half2_rn(v.z, v.w);
  *(uint2*)(a.dst[seg] + (size_t)j * 4) = make_uint2(*(uint32_t*)&p, *(uint32_t*)&q);
}

// ---------------- helpers ----------------
__device__ __forceinline__ void cp16(void* dst, const void* src) {
  uint32_t d = (uint32_t)__cvta_generic_to_shared(dst);
  asm volatile("cp.async.cg.shared.global [%0], [%1], 16;\n" :: "r"(d), "l"(src));
}
__device__ __forceinline__ void cp_commit() {
  asm volatile("cp.async.commit_group;\n");
}
template<int N> __device__ __forceinline__ void cp_wait() {
  asm volatile("cp.async.wait_group %0;\n" :: "n"(N));
}
__device__ __forceinline__ uint4 pack8(float4 f0, float4 f1) {
  __half2 a = __floats2half2_rn(f0.x, f0.y);
  __half2 b = __floats2half2_rn(f0.z, f0.w);
  __half2 c = __floats2half2_rn(f1.x, f1.y);
  __half2 d = __floats2half2_rn(f1.z, f1.w);
  return make_uint4(*(uint32_t*)&a, *(uint32_t*)&b, *(uint32_t*)&c, *(uint32_t*)&d);
}

using FragAcc  = wmma::fragment<wmma::accumulator, 16, 16, 16, float>;
using FragAccH = wmma::fragment<wmma::accumulator, 16, 16, 16, __half>;
using FragA    = wmma::fragment<wmma::matrix_a, 16, 16, 16, __half, wmma::row_major>;
using FragB    = wmma::fragment<wmma::matrix_b, 16, 16, 16, __half, wmma::row_major>;

// ===========================================================================
// branch12 (M=64, 256 threads, 2-deep): GEMM K1 -> relu -> h1 -> GEMM 256
// PAIR 0: A = [s | c | s*c]     PAIR 1: A = [s-c | |s-c|]
// smem: h1 @0 (33792), Bb[2] @33792/@50688 (16896 ea), Ab[2] @67584/@72704
// ===========================================================================
template<int PAIR, int K1>
__device__ __forceinline__ void branch12(
    char* smem, int tid, int tBase,
    const float* rS, const float* rC,
    const __half* __restrict__ W1, const float* __restrict__ b1,
    const __half* __restrict__ W2, const float* __restrict__ b2,
    __half* __restrict__ outp) {
  __half* h1 = (__half*)smem;
  __half* Bb[2] = { (__half*)(smem + 33792), (__half*)(smem + 50688) };
  __half* Ab[2] = { (__half*)(smem + 67584), (__half*)(smem + 72704) };
  float* bias32 = (float*)(smem + 33792);    // aliases Bb

  const int warp = tid >> 5;
  const int wm = warp >> 2, wn = warp & 3;   // 2x4 warps; tile 32x64
  const int row = tid >> 2;                  // 0..63
  const int c8 = (tid & 3) * 8;

  // bias b1 -> acc
  if (tid < 264) {
    float v = (tid < 256) ? b1[tid] : 0.f;
    #pragma unroll
    for (int r = 0; r < 16; r++) bias32[r * 264 + tid] = v;
  }
  __syncthreads();
  FragAcc acc[2][4];
  #pragma unroll
  for (int mi = 0; mi < 2; mi++)
    #pragma unroll
    for (int ni = 0; ni < 4; ni++)
      wmma::load_matrix_sync(acc[mi][ni], bias32 + wn * 64 + ni * 16, 264,
                             wmma::mem_row_major);
  __syncthreads();

  auto stageA = [&](int s, int buf) {
    const int k0 = s * 32;
    const int region = k0 >> 8;
    const int kk = (k0 & 255) + c8;
    float4 f0, f1;
    if constexpr (PAIR == 0) {
      if (region == 0)      { f0 = *(const float4*)(rS + kk); f1 = *(const float4*)(rS + kk + 4); }
      else if (region == 1) { f0 = *(const float4*)(rC + kk); f1 = *(const float4*)(rC + kk + 4); }
      else {
        float4 a0 = *(const float4*)(rS + kk), a1 = *(const float4*)(rS + kk + 4);
        float4 c0 = *(const float4*)(rC + kk), c1 = *(const float4*)(rC + kk + 4);
        f0 = make_float4(a0.x*c0.x, a0.y*c0.y, a0.z*c0.z, a0.w*c0.w);
        f1 = make_float4(a1.x*c1.x, a1.y*c1.y, a1.z*c1.z, a1.w*c1.w);
      }
    } else {
      float4 a0 = *(const float4*)(rS + kk), a1 = *(const float4*)(rS + kk + 4);
      float4 c0 = *(const float4*)(rC + kk), c1 = *(const float4*)(rC + kk + 4);
      f0 = make_float4(a0.x-c0.x, a0.y-c0.y, a0.z-c0.z, a0.w-c0.w);
      f1 = make_float4(a1.x-c1.x, a1.y-c1.y, a1.z-c1.z, a1.w-c1.w);
      if (region == 1) {
        f0 = make_float4(fabsf(f0.x), fabsf(f0.y), fabsf(f0.z), fabsf(f0.w));
        f1 = make_float4(fabsf(f1.x), fabsf(f1.y), fabsf(f1.z), fabsf(f1.w));
      }
    }
    *(uint4*)(Ab[buf] + row * 40 + c8) = pack8(f0, f1);
  };
  auto issueB = [&](const __half* W, int k0, int buf) {
    #pragma unroll
    for (int i = 0; i < 4; i++) {
      const int lin = tid + i * 256;
      const int br = lin >> 5, bc = (lin & 31) * 8;
      cp16(Bb[buf] + br * 264 + bc, W + (size_t)(k0 + br) * 256 + bc);
    }
    cp_commit();
  };

  // ---------------- GEMM 1 (K = K1, slab 32) ----------------
  constexpr int NS1 = K1 / 32;
  stageA(0, 0);
  issueB(W1, 0, 0);
  for (int s = 0; s < NS1; s++) {
    const int cur = s & 1;
    cp_wait<0>();
    __syncthreads();
    if (s + 1 < NS1) { stageA(s + 1, cur ^ 1); issueB(W1, (s + 1) * 32, cur ^ 1); }
    #pragma unroll
    for (int ks = 0; ks < 32; ks += 16) {
      FragA af[2]; FragB bf[4];
      #pragma unroll
      for (int mi = 0; mi < 2; mi++)
        wmma::load_matrix_sync(af[mi], Ab[cur] + (wm * 32 + mi * 16) * 40 + ks, 40);
      #pragma unroll
      for (int ni = 0; ni < 4; ni++)
        wmma::load_matrix_sync(bf[ni], Bb[cur] + ks * 264 + wn * 64 + ni * 16, 264);
      #pragma unroll
      for (int mi = 0; mi < 2; mi++)
        #pragma unroll
        for (int ni = 0; ni < 4; ni++)
          wmma::mma_sync(acc[mi][ni], af[mi], bf[ni], acc[mi][ni]);
    }
  }

  // epilogue 1: relu -> fp16 -> h1
  #pragma unroll
  for (int mi = 0; mi < 2; mi++)
    #pragma unroll
    for (int ni = 0; ni < 4; ni++) {
      FragAccH hf;
      #pragma unroll
      for (int e = 0; e < hf.num_elements; e++)
        hf.x[e] = __float2half(fmaxf(acc[mi][ni].x[e], 0.f));
      wmma::store_matrix_sync(h1 + (wm * 32 + mi * 16) * 264 + wn * 64 + ni * 16,
                              hf, 264, wmma::mem_row_major);
    }

  // bias b2 -> acc
  if (tid < 264) {
    float v = (tid < 256) ? b2[tid] : 0.f;
    #pragma unroll
    for (int r = 0; r < 16; r++) bias32[r * 264 + tid] = v;
  }
  __syncthreads();
  #pragma unroll
  for (int mi = 0; mi < 2; mi++)
    #pragma unroll
    for (int ni = 0; ni < 4; ni++)
      wmma::load_matrix_sync(acc[mi][ni], bias32 + wn * 64 + ni * 16, 264,
                             wmma::mem_row_major);
  __syncthreads();

  // ---------------- GEMM 2 (A = h1, K = 256, slab 32) ----------------
  issueB(W2, 0, 0);
  for (int s = 0; s < 8; s++) {
    const int cur = s & 1;
    cp_wait<0>();
    __syncthreads();
    if (s + 1 < 8) issueB(W2, (s + 1) * 32, cur ^ 1);
    #pragma unroll
    for (int ks = 0; ks < 32; ks += 16) {
      FragA af[2]; FragB bf[4];
      #pragma unroll
      for (int mi = 0; mi < 2; mi++)
        wmma::load_matrix_sync(af[mi], h1 + (wm * 32 + mi * 16) * 264 + s * 32 + ks, 264);
      #pragma unroll
      for (int ni = 0; ni < 4; ni++)
        wmma::load_matrix_sync(bf[ni], Bb[cur] + ks * 264 + wn * 64 + ni * 16, 264);
      #pragma unroll
      for (int mi = 0; mi < 2; mi++)
        #pragma unroll
        for (int ni = 0; ni < 4; ni++)
          wmma::mma_sync(acc[mi][ni], af[mi], bf[ni], acc[mi][ni]);
    }
  }

  // epilogue 2 -> global fp16 (bias pre-added)
  #pragma unroll
  for (int mi = 0; mi < 2; mi++)
    #pragma unroll
    for (int ni = 0; ni < 4; ni++) {
      FragAccH hf;
      #pragma unroll
      for (int e = 0; e < hf.num_elements; e++)
        hf.x[e] = __float2half(acc[mi][ni].x[e]);
      wmma::store_matrix_sync(outp + (size_t)(tBase + wm * 32 + mi * 16) * 256 +
                                  wn * 64 + ni * 16,
                              hf, 256, wmma::mem_row_major);
    }
}

// ===========================================================================
// fused14: both branches for the same 64 tokens. 256 threads, 2 CTAs/SM.
// ===========================================================================
__global__ __launch_bounds__(256, 2)
void fused14(const float* __restrict__ s_enc, const float* __restrict__ c_enc,
             const __half* __restrict__ W1, const float* __restrict__ b1,
             const __half* __restrict__ W2, const float* __restrict__ b2,
             const __half* __restrict__ W3, const float* __restrict__ b3,
             const __half* __restrict__ W4, const float* __restrict__ b4,
             __half* __restrict__ crossp, __half* __restrict__ difp) {
  extern __shared__ char smem[];
  const int tid = threadIdx.x;
  const int tBase = blockIdx.x * 64;
  const int row = tid >> 2;
  const int t_tok = tBase + row;
  const int bidx = t_tok >> 2, kidx = t_tok & 3;
  const float* rS = s_enc + ((size_t)bidx * NSTR + g_ti[kidx]) * D;
  const float* rC = c_enc + ((size_t)bidx * NSCA + g_tj[kidx]) * D;

  branch12<0, 768>(smem, tid, tBase, rS, rC, W1, b1, W2, b2, crossp);
  __syncthreads();
  branch12<1, 512>(smem, tid, tBase, rS, rC, W3, b3, W4, b4, difp);
}

// ===========================================================================
// fused56: 512 threads, M=64, K-slab 64 (fewer barriers).
//   GEMM5: 64x512 single pass, K=768, slab 64 (12 slabs) -> relu -> h3 64x520
//   GEMM6: 64x256, K=512, slab 64 (8 slabs) -> +b6 -> LN -> weighted sum
// smem: h3 @0 (66560), Bb[2] @66560/@133120 (66560 ea),
//       Ab[2] @199680/@208896 (64x72x2 = 9216 ea) = 218112 total.
//       bias32 aliases Bb, sC aliases h3.
// ===========================================================================
__global__ __launch_bounds__(512, 1)
void fused56(const __half* __restrict__ cross, const __half* __restrict__ dif,
             const float* __restrict__ s_enc, const float* __restrict__ c_enc,
             const __half* __restrict__ W5, const float* __restrict__ b5,
             const __half* __restrict__ W6, const float* __restrict__ b6,
             const float* __restrict__ lng, const float* __restrict__ lnb,
             float* __restrict__ outp) {
  extern __shared__ char smem[];
  __half* h3 = (__half*)smem;                                   // 64x520
  __half* Bb[2] = { (__half*)(smem + 66560), (__half*)(smem + 133120) };
  __half* Ab[2] = { (__half*)(smem + 199680), (__half*)(smem + 208896) };
  float* bias32 = (float*)(smem + 66560);                       // aliases Bb
  float* sC = (float*)smem;                                     // 64x260 aliases h3

  const int tid = threadIdx.x, warp = tid >> 5, lane = tid & 31;
  const int tBase = blockIdx.x * 64;

  // A staging: first 256 threads, 4 threads per row, 16 cols each
  const int row = (tid >> 2) & 63;
  const int colg = (tid & 3) * 16;
  const int t_tok = tBase + row;
  const int bidx = t_tok >> 2, kidx = t_tok & 3;
  const float* rS = s_enc + ((size_t)bidx * NSTR + g_ti[kidx]) * D;
  const float* rC = c_enc + ((size_t)bidx * NSCA + g_tj[kidx]) * D;

  // bias tile b5 (512-wide) -> acc
  if (tid < 520) {
    float v = (tid < 512) ? b5[tid] : 0.f;
    #pragma unroll
    for (int r = 0; r < 16; r++) bias32[r * 520 + tid] = v;
  }
  __syncthreads();
  const int wm5 = warp >> 3, wn5 = warp & 7;  // 2x8 warps; warp tile 32x64
  FragAcc acc5[2][4];
  #pragma unroll
  for (int mi = 0; mi < 2; mi++)
    #pragma unroll
    for (int ni = 0; ni < 4; ni++)
      wmma::load_matrix_sync(acc5[mi][ni], bias32 + wn5 * 64 + ni * 16, 520,
                             wmma::mem_row_major);
  __syncthreads();

  auto stageA5 = [&](int s, int buf) {
    if (tid >= 256) return;
    const int k0 = s * 64;                    // slab-64; region-aligned
    const int region = k0 >> 8;
    const int kk = (k0 & 255) + colg;
    if (region < 2) {
      const __half* src = (region ? dif : cross) + (size_t)t_tok * 256 + kk;
      cp16(Ab[buf] + row * 72 + colg, src);
      cp16(Ab[buf] + row * 72 + colg + 8, src + 8);
    } else {
      #pragma unroll
      for (int h = 0; h < 2; h++) {
        const int c8 = colg + h * 8;
        const int k2 = (k0 & 255) + c8;
        float4 a0 = *(const float4*)(rS + k2), a1 = *(const float4*)(rS + k2 + 4);
        float4 c0 = *(const float4*)(rC + k2), c1 = *(const float4*)(rC + k2 + 4);
        float4 f0 = make_float4(a0.x*c0.x, a0.y*c0.y, a0.z*c0.z, a0.w*c0.w);
        float4 f1 = make_float4(a1.x*c1.x, a1.y*c1.y, a1.z*c1.z, a1.w*c1.w);
        *(uint4*)(Ab[buf] + row * 72 + c8) = pack8(f0, f1);
      }
    }
  };
  auto issueB5 = [&](int k0, int buf) {
    #pragma unroll
    for (int i = 0; i < 8; i++) {
      const int lin = tid + i * 512;          // 0..4095
      const int br = lin >> 6, bc = (lin & 63) * 8;
      cp16(Bb[buf] + br * 520 + bc, W5 + (size_t)(k0 + br) * 512 + bc);
    }
  };

  // ---------------- GEMM5: 12 slabs of 64 ----------------
  stageA5(0, 0);
  issueB5(0, 0);
  cp_commit();
  for (int s = 0; s < 12; s++) {
    const int cur = s & 1;
    cp_wait<0>();
    __syncthreads();
    if (s + 1 < 12) {
      stageA5(s + 1, cur ^ 1);
      issueB5((s + 1) * 64, cur ^ 1);
      cp_commit();
    }
    #pragma unroll
    for (int ks = 0; ks < 64; ks += 16) {
      FragA af[2]; FragB bf[4];
      #pragma unroll
      for (int mi = 0; mi < 2; mi++)
        wmma::load_matrix_sync(af[mi], Ab[cur] + (wm5 * 32 + mi * 16) * 72 + ks, 72);
      #pragma unroll
      for (int ni = 0; ni < 4; ni++)
        wmma::load_matrix_sync(bf[ni], Bb[cur] + ks * 520 + wn5 * 64 + ni * 16, 520);
      #pragma unroll
      for (int mi = 0; mi < 2; mi++)
        #pragma unroll
        for (int ni = 0; ni < 4; ni++)
          wmma::mma_sync(acc5[mi][ni], af[mi], bf[ni], acc5[mi][ni]);
    }
  }

  // epilogue 5: relu -> fp16 -> h3
  #pragma unroll
  for (int mi = 0; mi < 2; mi++)
    #pragma unroll
    for (int ni = 0; ni < 4; ni++) {
      FragAccH hf;
      #pragma unroll
      for (int e = 0; e < hf.num_elements; e++)
        hf.x[e] = __float2half(fmaxf(acc5[mi][ni].x[e], 0.f));
      wmma::store_matrix_sync(h3 + (wm5 * 32 + mi * 16) * 520 + wn5 * 64 + ni * 16,
                              hf, 520, wmma::mem_row_major);
    }

  // ---------------- GEMM6: 64x256, K=512, 8 slabs of 64 (A = h3) ----------------
  const int wm6 = warp >> 2, wn6 = warp & 3;  // 4x4 warps; warp tile 16x64
  FragAcc acc6[4];
  #pragma unroll
  for (int ni = 0; ni < 4; ni++) wmma::fill_fragment(acc6[ni], 0.f);

  auto issueB6 = [&](int k0, int buf) {
    #pragma unroll
    for (int i = 0; i < 4; i++) {
      const int lin = tid + i * 512;          // 0..2047
      const int br = lin >> 5, bc = (lin & 31) * 8;
      cp16(Bb[buf] + br * 264 + bc, W6 + (size_t)(k0 + br) * 256 + bc);
    }
    cp_commit();
  };
  issueB6(0, 0);
  for (int s = 0; s < 8; s++) {
    const int cur = s & 1;
    cp_wait<0>();
    __syncthreads();
    if (s + 1 < 8) issueB6((s + 1) * 64, cur ^ 1);
    #pragma unroll
    for (int ks = 0; ks < 64; ks += 16) {
      FragA af; FragB bf[4];
      wmma::load_matrix_sync(af, h3 + (wm6 * 16) * 520 + s * 64 + ks, 520);
      #pragma unroll
      for (int ni = 0; ni < 4; ni++)
        wmma::load_matrix_sync(bf[ni], Bb[cur] + ks * 264 + wn6 * 64 + ni * 16, 264);
      #pragma unroll
      for (int ni = 0; ni < 4; ni++)
        wmma::mma_sync(acc6[ni], af, bf[ni], acc6[ni]);
    }
  }

  __syncthreads();  // all h3 reads done before overwrite with sC
  #pragma unroll
  for (int ni = 0; ni < 4; ni++)
    wmma::store_matrix_sync(sC + (wm6 * 16) * 260 + wn6 * 64 + ni * 16,
                            acc6[ni], 260, wmma::mem_row_major);
  __syncthreads();

  // LN + weighted top-k sum. Warp w owns rows 4w..4w+3 (= one batch).
  {
    const int w = warp;
    float b6c[8], gc[8], bc[8];
    #pragma unroll
    for (int j = 0; j < 8; j++) {
      const int c = lane + 32 * j;
      b6c[j] = b6[c]; gc[j] = lng[c]; bc[j] = lnb[c];
    }
    float o[8];
    #pragma unroll
    for (int j = 0; j < 8; j++) o[j] = 0.f;
    #pragma unroll
    for (int k = 0; k < 4; k++) {
      const int r = 4 * w + k;
      float x[8];
      float s1 = 0.f, s2 = 0.f;
      #pragma unroll
      for (int j = 0; j < 8; j++) {
        float xv = sC[r * 260 + lane + 32 * j] + b6c[j];
        x[j] = xv; s1 += xv; s2 += xv * xv;
      }
      #pragma unroll
      for (int off = 16; off > 0; off >>= 1) {
        s1 += __shfl_xor_sync(0xffffffffu, s1, off);
        s2 += __shfl_xor_sync(0xffffffffu, s2, off);
      }
      const float mu  = s1 * (1.f / 256.f);
      const float var = s2 * (1.f / 256.f) - mu * mu;
      const float inv = rsqrtf(var + LN_EPS);
      const float wk  = g_w[k];
      #pragma unroll
      for (int j = 0; j < 8; j++) o[j] += wk * (x[j] - mu) * inv;
    }
    const int ob = (tBase >> 2) + w;
    #pragma unroll
    for (int j = 0; j < 8; j++) {
      const int c = lane + 32 * j;
      outp[(size_t)ob * 256 + c] = o[j] * gc[j] + bc[j];
    }
  }
}

// ---------------------------------------------------------------------------
extern "C" void kernel_launch(void* const* d_in, const int* in_sizes, int n_in,
                              void* d_out, int out_size) {
  const float* str   = (const float*)d_in[0];
  const float* sca   = (const float*)d_in[1];
  const float* pair  = (const float*)d_in[2];
  const float* temp  = (const float*)d_in[3];
  const float* cm_w1 = (const float*)d_in[4];
  const float* cm_b1 = (const float*)d_in[5];
  const float* cm_w2 = (const float*)d_in[6];
  const float* cm_b2 = (const float*)d_in[7];
  const float* df_w1 = (const float*)d_in[8];
  const float* df_b1 = (const float*)d_in[9];
  const float* df_w2 = (const float*)d_in[10];
  const float* df_b2 = (const float*)d_in[11];
  const float* fu_w1 = (const float*)d_in[12];
  const float* fu_b1 = (const float*)d_in[13];
  const float* fu_w2 = (const float*)d_in[14];
  const float* fu_b2 = (const float*)d_in[15];
  const float* lng   = (const float*)d_in[16];
  const float* lnb   = (const float*)d_in[17];
  float* out = (float*)d_out;

  __half *crossh, *difh, *hw1, *hw2, *hw3, *hw4, *hw5, *hw6;
  cudaGetSymbolAddress((void**)&crossh, g_crossh);
  cudaGetSymbolAddress((void**)&difh,   g_difh);
  cudaGetSymbolAddress((void**)&hw1,    g_hw1);
  cudaGetSymbolAddress((void**)&hw2,    g_hw2);
  cudaGetSymbolAddress((void**)&hw3,    g_hw3);
  cudaGetSymbolAddress((void**)&hw4,    g_hw4);
  cudaGetSymbolAddress((void**)&hw5,    g_hw5);
  cudaGetSymbolAddress((void**)&hw6,    g_hw6);

  prep_kernel<<<1, 32>>>(pair, temp);

  CvtArgs ca;
  ca.src[0] = cm_w1; ca.dst[0] = hw1;
  ca.src[1] = cm_w2; ca.dst[1] = hw2;
  ca.src[2] = df_w1; ca.dst[2] = hw3;
  ca.src[3] = df_w2; ca.dst[3] = hw4;
  ca.src[4] = fu_w1; ca.dst[4] = hw5;
  ca.src[5] = fu_w2; ca.dst[5] = hw6;
  ca.cum[0] = 0;
  ca.cum[1] = 49152;
  ca.cum[2] = 65536;
  ca.cum[3] = 98304;
  ca.cum[4] = 114688;
  ca.cum[5] = 212992;
  ca.cum[6] = 245760;
  cvt_all<<<(245760 + 255) / 256, 256>>>(ca);

  const size_t SM_AB = 77824;    // 2 CTAs/SM
  const size_t SM_C  = 218112;   // 1 CTA/SM

  { auto k = fused14;
    cudaFuncSetAttribute(k, cudaFuncAttributeMaxDynamicSharedMemorySize, (int)SM_AB);
    k<<<T_TOK / 64, 256, SM_AB>>>(str, sca, hw1, cm_b1, hw2, cm_b2,
                                  hw3, df_b1, hw4, df_b2, crossh, difh); }
  { auto k = fused56;
    cudaFuncSetAttribute(k, cudaFuncAttributeMaxDynamicSharedMemorySize, (int)SM_C);
    k<<<T_TOK / 64, 512, SM_C>>>(crossh, difh, str, sca, hw5, fu_b1, hw6, fu_b2,
                                 lng, lnb, out); }
}

// round 17
// speedup vs baseline: 1.0345x; 1.0345x over previous
#include <cuda_runtime.h>
#include <cuda_fp16.h>
#include <mma.h>
#include <math.h>
#include <stdint.h>

using namespace nvcuda;

constexpr int D = 256;
constexpr int NSTR = 6;
constexpr int NSCA = 20;
constexpr int TK = 4;
constexpr int BATCH = 32768;
constexpr int T_TOK = BATCH * TK;   // 131072
constexpr float LN_EPS = 1e-5f;

// ---------------- device scratch ----------------
__device__ float g_w[TK];
__device__ int   g_ti[TK];
__device__ int   g_tj[TK];

__device__ __align__(16) __half g_crossh[(size_t)T_TOK * D];  // cross_f + cm_b2
__device__ __align__(16) __half g_difh  [(size_t)T_TOK * D];  // diff_f + df_b2

__device__ __align__(16) __half g_hw1[768 * 256];
__device__ __align__(16) __half g_hw2[256 * 256];
__device__ __align__(16) __half g_hw3[512 * 256];
__device__ __align__(16) __half g_hw4[256 * 256];
__device__ __align__(16) __half g_hw5[768 * 512];
__device__ __align__(16) __half g_hw6[512 * 256];

// ---------------- prep: top-k + softmax ----------------
__global__ void prep_kernel(const float* __restrict__ scores,
                            const float* __restrict__ tempp) {
  if (threadIdx.x != 0) return;
  const int NTOT = NSTR * NSCA;
  bool used[NSTR * NSCA] = {};
  float vals[TK]; int idx[TK];
  for (int r = 0; r < TK; r++) {
    float best = -INFINITY; int bi = 0;
    for (int i = 0; i < NTOT; i++)
      if (!used[i]) { float v = scores[i]; if (v > best) { best = v; bi = i; } }
    used[bi] = true; vals[r] = best; idx[r] = bi;
  }
  float tmp = fmaxf(tempp[0], 0.1f);
  float m = vals[0], e[TK], se = 0.f;
  for (int r = 0; r < TK; r++) { e[r] = expf((vals[r] - m) / tmp); se += e[r]; }
  for (int r = 0; r < TK; r++) {
    g_w[r]  = e[r] / se;
    g_ti[r] = idx[r] / NSCA;
    g_tj[r] = idx[r] % NSCA;
  }
}

// ---------------- single-launch fp32->fp16 weight conversion ----------------
struct CvtArgs {
  const float* src[6];
  __half* dst[6];
  int cum[7];
};
__global__ void cvt_all(CvtArgs a) {
  int i = blockIdx.x * blockDim.x + threadIdx.x;
  if (i >= a.cum[6]) return;
  int seg = 0;
  #pragma unroll
  for (int s = 1; s < 6; s++) seg += (i >= a.cum[s]) ? 1 : 0;
  const int j = i - a.cum[seg];
  float4 v = *(const float4*)(a.src[seg] + (size_t)j * 4);
  __half2 p = __floats2half2_rn(v.x, v.y);
  __half2 q = __floats2half2_rn(v.z, v.w);
  *(uint2*)(a.dst[seg] + (size_t)j * 4) = make_uint2(*(uint32_t*)&p, *(uint32_t*)&q);
}

// ---------------- helpers ----------------
__device__ __forceinline__ void cp16(void* dst, const void* src) {
  uint32_t d = (uint32_t)__cvta_generic_to_shared(dst);
  asm volatile("cp.async.cg.shared.global [%0], [%1], 16;\n" :: "r"(d), "l"(src));
}
__device__ __forceinline__ void cp_commit() {
  asm volatile("cp.async.commit_group;\n");
}
template<int N> __device__ __forceinline__ void cp_wait() {
  asm volatile("cp.async.wait_group %0;\n" :: "n"(N));
}
__device__ __forceinline__ uint4 pack8(float4 f0, float4 f1) {
  __half2 a = __floats2half2_rn(f0.x, f0.y);
  __half2 b = __floats2half2_rn(f0.z, f0.w);
  __half2 c = __floats2half2_rn(f1.x, f1.y);
  __half2 d = __floats2half2_rn(f1.z, f1.w);
  return make_uint4(*(uint32_t*)&a, *(uint32_t*)&b, *(uint32_t*)&c, *(uint32_t*)&d);
}

using FragAcc  = wmma::fragment<wmma::accumulator, 16, 16, 16, float>;
using FragAccH = wmma::fragment<wmma::accumulator, 16, 16, 16, __half>;
using FragA    = wmma::fragment<wmma::matrix_a, 16, 16, 16, __half, wmma::row_major>;
using FragB    = wmma::fragment<wmma::matrix_b, 16, 16, 16, __half, wmma::row_major>;

// ===========================================================================
// branch12 (M=64, 256 threads, 2-deep, reg-pipelined fragments)
// PAIR 0: A = [s | c | s*c]     PAIR 1: A = [s-c | |s-c|]
// smem: h1 @0 (33792), Bb[2] @33792/@50688 (16896 ea), Ab[2] @67584/@72704
// ===========================================================================
template<int PAIR, int K1>
__device__ __forceinline__ void branch12(
    char* smem, int tid, int tBase,
    const float* rS, const float* rC,
    const __half* __restrict__ W1, const float* __restrict__ b1,
    const __half* __restrict__ W2, const float* __restrict__ b2,
    __half* __restrict__ outp) {
  __half* h1 = (__half*)smem;
  __half* Bb[2] = { (__half*)(smem + 33792), (__half*)(smem + 50688) };
  __half* Ab[2] = { (__half*)(smem + 67584), (__half*)(smem + 72704) };
  float* bias32 = (float*)(smem + 33792);    // aliases Bb

  const int warp = tid >> 5;
  const int wm = warp >> 2, wn = warp & 3;   // 2x4 warps; tile 32x64
  const int row = tid >> 2;                  // 0..63
  const int c8 = (tid & 3) * 8;

  // bias b1 -> acc
  if (tid < 264) {
    float v = (tid < 256) ? b1[tid] : 0.f;
    #pragma unroll
    for (int r = 0; r < 16; r++) bias32[r * 264 + tid] = v;
  }
  __syncthreads();
  FragAcc acc[2][4];
  #pragma unroll
  for (int mi = 0; mi < 2; mi++)
    #pragma unroll
    for (int ni = 0; ni < 4; ni++)
      wmma::load_matrix_sync(acc[mi][ni], bias32 + wn * 64 + ni * 16, 264,
                             wmma::mem_row_major);
  __syncthreads();

  auto stageA = [&](int s, int buf) {
    const int k0 = s * 32;
    const int region = k0 >> 8;
    const int kk = (k0 & 255) + c8;
    float4 f0, f1;
    if constexpr (PAIR == 0) {
      if (region == 0)      { f0 = *(const float4*)(rS + kk); f1 = *(const float4*)(rS + kk + 4); }
      else if (region == 1) { f0 = *(const float4*)(rC + kk); f1 = *(const float4*)(rC + kk + 4); }
      else {
        float4 a0 = *(const float4*)(rS + kk), a1 = *(const float4*)(rS + kk + 4);
        float4 c0 = *(const float4*)(rC + kk), c1 = *(const float4*)(rC + kk + 4);
        f0 = make_float4(a0.x*c0.x, a0.y*c0.y, a0.z*c0.z, a0.w*c0.w);
        f1 = make_float4(a1.x*c1.x, a1.y*c1.y, a1.z*c1.z, a1.w*c1.w);
      }
    } else {
      float4 a0 = *(const float4*)(rS + kk), a1 = *(const float4*)(rS + kk + 4);
      float4 c0 = *(const float4*)(rC + kk), c1 = *(const float4*)(rC + kk + 4);
      f0 = make_float4(a0.x-c0.x, a0.y-c0.y, a0.z-c0.z, a0.w-c0.w);
      f1 = make_float4(a1.x-c1.x, a1.y-c1.y, a1.z-c1.z, a1.w-c1.w);
      if (region == 1) {
        f0 = make_float4(fabsf(f0.x), fabsf(f0.y), fabsf(f0.z), fabsf(f0.w));
        f1 = make_float4(fabsf(f1.x), fabsf(f1.y), fabsf(f1.z), fabsf(f1.w));
      }
    }
    *(uint4*)(Ab[buf] + row * 40 + c8) = pack8(f0, f1);
  };
  auto issueB = [&](const __half* W, int k0, int buf) {
    #pragma unroll
    for (int i = 0; i < 4; i++) {
      const int lin = tid + i * 256;
      const int br = lin >> 5, bc = (lin & 31) * 8;
      cp16(Bb[buf] + br * 264 + bc, W + (size_t)(k0 + br) * 256 + bc);
    }
    cp_commit();
  };

  FragA af[2][2]; FragB bf[2][4];
  auto loadFr = [&](int set, const __half* Amat, int lda, int aoff, int buf, int ks) {
    #pragma unroll
    for (int mi = 0; mi < 2; mi++)
      wmma::load_matrix_sync(af[set][mi],
                             Amat + (wm * 32 + mi * 16) * lda + aoff + ks, lda);
    #pragma unroll
    for (int ni = 0; ni < 4; ni++)
      wmma::load_matrix_sync(bf[set][ni],
                             Bb[buf] + ks * 264 + wn * 64 + ni * 16, 264);
  };
  auto mmaFr = [&](int set) {
    #pragma unroll
    for (int mi = 0; mi < 2; mi++)
      #pragma unroll
      for (int ni = 0; ni < 4; ni++)
        wmma::mma_sync(acc[mi][ni], af[set][mi], bf[set][ni], acc[mi][ni]);
  };

  // ---------------- GEMM 1 (K = K1, slab 32, pipelined frags) ----------------
  constexpr int NS1 = K1 / 32;
  stageA(0, 0);
  issueB(W1, 0, 0);
  for (int s = 0; s < NS1; s++) {
    const int cur = s & 1;
    cp_wait<0>();
    __syncthreads();
    loadFr(0, Ab[cur], 40, 0, cur, 0);          // frags for ks=0 first
    if (s + 1 < NS1) { stageA(s + 1, cur ^ 1); issueB(W1, (s + 1) * 32, cur ^ 1); }
    loadFr(1, Ab[cur], 40, 0, cur, 16);         // prefetch ks=16 frags
    mmaFr(0);
    mmaFr(1);
  }

  // epilogue 1: relu -> fp16 -> h1
  #pragma unroll
  for (int mi = 0; mi < 2; mi++)
    #pragma unroll
    for (int ni = 0; ni < 4; ni++) {
      FragAccH hf;
      #pragma unroll
      for (int e = 0; e < hf.num_elements; e++)
        hf.x[e] = __float2half(fmaxf(acc[mi][ni].x[e], 0.f));
      wmma::store_matrix_sync(h1 + (wm * 32 + mi * 16) * 264 + wn * 64 + ni * 16,
                              hf, 264, wmma::mem_row_major);
    }

  // bias b2 -> acc
  if (tid < 264) {
    float v = (tid < 256) ? b2[tid] : 0.f;
    #pragma unroll
    for (int r = 0; r < 16; r++) bias32[r * 264 + tid] = v;
  }
  __syncthreads();
  #pragma unroll
  for (int mi = 0; mi < 2; mi++)
    #pragma unroll
    for (int ni = 0; ni < 4; ni++)
      wmma::load_matrix_sync(acc[mi][ni], bias32 + wn * 64 + ni * 16, 264,
                             wmma::mem_row_major);
  __syncthreads();

  // ---------------- GEMM 2 (A = h1, K = 256, slab 32, pipelined) ----------------
  issueB(W2, 0, 0);
  for (int s = 0; s < 8; s++) {
    const int cur = s & 1;
    cp_wait<0>();
    __syncthreads();
    loadFr(0, h1, 264, s * 32, cur, 0);
    if (s + 1 < 8) issueB(W2, (s + 1) * 32, cur ^ 1);
    loadFr(1, h1, 264, s * 32, cur, 16);
    mmaFr(0);
    mmaFr(1);
  }

  // epilogue 2 -> global fp16 (bias pre-added)
  #pragma unroll
  for (int mi = 0; mi < 2; mi++)
    #pragma unroll
    for (int ni = 0; ni < 4; ni++) {
      FragAccH hf;
      #pragma unroll
      for (int e = 0; e < hf.num_elements; e++)
        hf.x[e] = __float2half(acc[mi][ni].x[e]);
      wmma::store_matrix_sync(outp + (size_t)(tBase + wm * 32 + mi * 16) * 256 +
                                  wn * 64 + ni * 16,
                              hf, 256, wmma::mem_row_major);
    }
}

// ===========================================================================
// fused14: both branches for the same 64 tokens. 256 threads, 2 CTAs/SM.
// ===========================================================================
__global__ __launch_bounds__(256, 2)
void fused14(const float* __restrict__ s_enc, const float* __restrict__ c_enc,
             const __half* __restrict__ W1, const float* __restrict__ b1,
             const __half* __restrict__ W2, const float* __restrict__ b2,
             const __half* __restrict__ W3, const float* __restrict__ b3,
             const __half* __restrict__ W4, const float* __restrict__ b4,
             __half* __restrict__ crossp, __half* __restrict__ difp) {
  extern __shared__ char smem[];
  const int tid = threadIdx.x;
  const int tBase = blockIdx.x * 64;
  const int row = tid >> 2;
  const int t_tok = tBase + row;
  const int bidx = t_tok >> 2, kidx = t_tok & 3;
  const float* rS = s_enc + ((size_t)bidx * NSTR + g_ti[kidx]) * D;
  const float* rC = c_enc + ((size_t)bidx * NSCA + g_tj[kidx]) * D;

  branch12<0, 768>(smem, tid, tBase, rS, rC, W1, b1, W2, b2, crossp);
  __syncthreads();
  branch12<1, 512>(smem, tid, tBase, rS, rC, W3, b3, W4, b4, difp);
}

// ===========================================================================
// fused56: 512 threads, M=64, K-slab 64, reg-pipelined fragments.
//   GEMM5: 64x512 single pass, K=768, slab 64 (12 slabs) -> relu -> h3 64x520
//   GEMM6: 64x256, K=512, slab 64 (8 slabs) -> +b6 -> LN -> weighted sum
// smem: h3 @0 (66560), Bb[2] @66560/@133120 (66560 ea),
//       Ab[2] @199680/@208896 (9216 ea) = 218112. bias32/sC alias.
// ===========================================================================
__global__ __launch_bounds__(512, 1)
void fused56(const __half* __restrict__ cross, const __half* __restrict__ dif,
             const float* __restrict__ s_enc, const float* __restrict__ c_enc,
             const __half* __restrict__ W5, const float* __restrict__ b5,
             const __half* __restrict__ W6, const float* __restrict__ b6,
             const float* __restrict__ lng, const float* __restrict__ lnb,
             float* __restrict__ outp) {
  extern __shared__ char smem[];
  __half* h3 = (__half*)smem;                                   // 64x520
  __half* Bb[2] = { (__half*)(smem + 66560), (__half*)(smem + 133120) };
  __half* Ab[2] = { (__half*)(smem + 199680), (__half*)(smem + 208896) };
  float* bias32 = (float*)(smem + 66560);                       // aliases Bb
  float* sC = (float*)smem;                                     // 64x260 aliases h3

  const int tid = threadIdx.x, warp = tid >> 5, lane = tid & 31;
  const int tBase = blockIdx.x * 64;

  // A staging: first 256 threads, 4 threads per row, 16 cols each
  const int row = (tid >> 2) & 63;
  const int colg = (tid & 3) * 16;
  const int t_tok = tBase + row;
  const int bidx = t_tok >> 2, kidx = t_tok & 3;
  const float* rS = s_enc + ((size_t)bidx * NSTR + g_ti[kidx]) * D;
  const float* rC = c_enc + ((size_t)bidx * NSCA + g_tj[kidx]) * D;

  // bias tile b5 (512-wide) -> acc
  if (tid < 520) {
    float v = (tid < 512) ? b5[tid] : 0.f;
    #pragma unroll
    for (int r = 0; r < 16; r++) bias32[r * 520 + tid] = v;
  }
  __syncthreads();
  const int wm5 = warp >> 3, wn5 = warp & 7;  // 2x8 warps; warp tile 32x64
  FragAcc acc5[2][4];
  #pragma unroll
  for (int mi = 0; mi < 2; mi++)
    #pragma unroll
    for (int ni = 0; ni < 4; ni++)
      wmma::load_matrix_sync(acc5[mi][ni], bias32 + wn5 * 64 + ni * 16, 520,
                             wmma::mem_row_major);
  __syncthreads();

  auto stageA5 = [&](int s, int buf) {
    if (tid >= 256) return;
    const int k0 = s * 64;                    // slab-64; region-aligned
    const int region = k0 >> 8;
    const int kk = (k0 & 255) + colg;
    if (region < 2) {
      const __half* src = (region ? dif : cross) + (size_t)t_tok * 256 + kk;
      cp16(Ab[buf] + row * 72 + colg, src);
      cp16(Ab[buf] + row * 72 + colg + 8, src + 8);
    } else {
      #pragma unroll
      for (int h = 0; h < 2; h++) {
        const int c8 = colg + h * 8;
        const int k2 = (k0 & 255) + c8;
        float4 a0 = *(const float4*)(rS + k2), a1 = *(const float4*)(rS + k2 + 4);
        float4 c0 = *(const float4*)(rC + k2), c1 = *(const float4*)(rC + k2 + 4);
        float4 f0 = make_float4(a0.x*c0.x, a0.y*c0.y, a0.z*c0.z, a0.w*c0.w);
        float4 f1 = make_float4(a1.x*c1.x, a1.y*c1.y, a1.z*c1.z, a1.w*c1.w);
        *(uint4*)(Ab[buf] + row * 72 + c8) = pack8(f0, f1);
      }
    }
  };
  auto issueB5 = [&](int k0, int buf) {
    #pragma unroll
    for (int i = 0; i < 8; i++) {
      const int lin = tid + i * 512;          // 0..4095
      const int br = lin >> 6, bc = (lin & 63) * 8;
      cp16(Bb[buf] + br * 520 + bc, W5 + (size_t)(k0 + br) * 512 + bc);
    }
  };

  // ---------------- GEMM5: 12 slabs of 64, pipelined frags ----------------
  FragA af[2][2]; FragB bf[2][4];
  auto loadFr5 = [&](int set, int buf, int ks) {
    #pragma unroll
    for (int mi = 0; mi < 2; mi++)
      wmma::load_matrix_sync(af[set][mi],
                             Ab[buf] + (wm5 * 32 + mi * 16) * 72 + ks, 72);
    #pragma unroll
    for (int ni = 0; ni < 4; ni++)
      wmma::load_matrix_sync(bf[set][ni],
                             Bb[buf] + ks * 520 + wn5 * 64 + ni * 16, 520);
  };
  auto mmaFr5 = [&](int set) {
    #pragma unroll
    for (int mi = 0; mi < 2; mi++)
      #pragma unroll
      for (int ni = 0; ni < 4; ni++)
        wmma::mma_sync(acc5[mi][ni], af[set][mi], bf[set][ni], acc5[mi][ni]);
  };

  stageA5(0, 0);
  issueB5(0, 0);
  cp_commit();
  for (int s = 0; s < 12; s++) {
    const int cur = s & 1;
    cp_wait<0>();
    __syncthreads();
    loadFr5(0, cur, 0);
    if (s + 1 < 12) {
      stageA5(s + 1, cur ^ 1);
      issueB5((s + 1) * 64, cur ^ 1);
      cp_commit();
    }
    #pragma unroll
    for (int k16 = 0; k16 < 4; k16++) {
      const int c = k16 & 1, n = c ^ 1;
      if (k16 + 1 < 4) loadFr5(n, cur, (k16 + 1) * 16);
      mmaFr5(c);
    }
  }

  // epilogue 5: relu -> fp16 -> h3
  #pragma unroll
  for (int mi = 0; mi < 2; mi++)
    #pragma unroll
    for (int ni = 0; ni < 4; ni++) {
      FragAccH hf;
      #pragma unroll
      for (int e = 0; e < hf.num_elements; e++)
        hf.x[e] = __float2half(fmaxf(acc5[mi][ni].x[e], 0.f));
      wmma::store_matrix_sync(h3 + (wm5 * 32 + mi * 16) * 520 + wn5 * 64 + ni * 16,
                              hf, 520, wmma::mem_row_major);
    }

  // ---------------- GEMM6: 64x256, K=512, 8 slabs of 64, pipelined ----------------
  const int wm6 = warp >> 2, wn6 = warp & 3;  // 4x4 warps; warp tile 16x64
  FragAcc acc6[4];
  #pragma unroll
  for (int ni = 0; ni < 4; ni++) wmma::fill_fragment(acc6[ni], 0.f);

  auto issueB6 = [&](int k0, int buf) {
    #pragma unroll
    for (int i = 0; i < 4; i++) {
      const int lin = tid + i * 512;          // 0..2047
      const int br = lin >> 5, bc = (lin & 31) * 8;
      cp16(Bb[buf] + br * 264 + bc, W6 + (size_t)(k0 + br) * 256 + bc);
    }
    cp_commit();
  };
  FragA af6[2]; FragB bf6[2][4];
  auto loadFr6 = [&](int set, int buf, int s, int ks) {
    wmma::load_matrix_sync(af6[set], h3 + (wm6 * 16) * 520 + s * 64 + ks, 520);
    #pragma unroll
    for (int ni = 0; ni < 4; ni++)
      wmma::load_matrix_sync(bf6[set][ni],
                             Bb[buf] + ks * 264 + wn6 * 64 + ni * 16, 264);
  };
  auto mmaFr6 = [&](int set) {
    #pragma unroll
    for (int ni = 0; ni < 4; ni++)
      wmma::mma_sync(acc6[ni], af6[set], bf6[set][ni], acc6[ni]);
  };

  issueB6(0, 0);
  for (int s = 0; s < 8; s++) {
    const int cur = s & 1;
    cp_wait<0>();
    __syncthreads();
    loadFr6(0, cur, s, 0);
    if (s + 1 < 8) issueB6((s + 1) * 64, cur ^ 1);
    #pragma unroll
    for (int k16 = 0; k16 < 4; k16++) {
      const int c = k16 & 1, n = c ^ 1;
      if (k16 + 1 < 4) loadFr6(n, cur, s, (k16 + 1) * 16);
      mmaFr6(c);
    }
  }

  __syncthreads();  // all h3 reads done before overwrite with sC
  #pragma unroll
  for (int ni = 0; ni < 4; ni++)
    wmma::store_matrix_sync(sC + (wm6 * 16) * 260 + wn6 * 64 + ni * 16,
                            acc6[ni], 260, wmma::mem_row_major);
  __syncthreads();

  // LN + weighted top-k sum. Warp w owns rows 4w..4w+3 (= one batch).
  {
    const int w = warp;
    float b6c[8], gc[8], bc[8];
    #pragma unroll
    for (int j = 0; j < 8; j++) {
      const int c = lane + 32 * j;
      b6c[j] = b6[c]; gc[j] = lng[c]; bc[j] = lnb[c];
    }
    float o[8];
    #pragma unroll
    for (int j = 0; j < 8; j++) o[j] = 0.f;
    #pragma unroll
    for (int k = 0; k < 4; k++) {
      const int r = 4 * w + k;
      float x[8];
      float s1 = 0.f, s2 = 0.f;
      #pragma unroll
      for (int j = 0; j < 8; j++) {
        float xv = sC[r * 260 + lane + 32 * j] + b6c[j];
        x[j] = xv; s1 += xv; s2 += xv * xv;
      }
      #pragma unroll
      for (int off = 16; off > 0; off >>= 1) {
        s1 += __shfl_xor_sync(0xffffffffu, s1, off);
        s2 += __shfl_xor_sync(0xffffffffu, s2, off);
      }
      const float mu  = s1 * (1.f / 256.f);
      const float var = s2 * (1.f / 256.f) - mu * mu;
      const float inv = rsqrtf(var + LN_EPS);
      const float wk  = g_w[k];
      #pragma unroll
      for (int j = 0; j < 8; j++) o[j] += wk * (x[j] - mu) * inv;
    }
    const int ob = (tBase >> 2) + w;
    #pragma unroll
    for (int j = 0; j < 8; j++) {
      const int c = lane + 32 * j;
      outp[(size_t)ob * 256 + c] = o[j] * gc[j] + bc[j];
    }
  }
}

// ---------------------------------------------------------------------------
extern "C" void kernel_launch(void* const* d_in, const int* in_sizes, int n_in,
                              void* d_out, int out_size) {
  const float* str   = (const float*)d_in[0];
  const float* sca   = (const float*)d_in[1];
  const float* pair  = (const float*)d_in[2];
  const float* temp  = (const float*)d_in[3];
  const float* cm_w1 = (const float*)d_in[4];
  const float* cm_b1 = (const float*)d_in[5];
  const float* cm_w2 = (const float*)d_in[6];
  const float* cm_b2 = (const float*)d_in[7];
  const float* df_w1 = (const float*)d_in[8];
  const float* df_b1 = (const float*)d_in[9];
  const float* df_w2 = (const float*)d_in[10];
  const float* df_b2 = (const float*)d_in[11];
  const float* fu_w1 = (const float*)d_in[12];
  const float* fu_b1 = (const float*)d_in[13];
  const float* fu_w2 = (const float*)d_in[14];
  const float* fu_b2 = (const float*)d_in[15];
  const float* lng   = (const float*)d_in[16];
  const float* lnb   = (const float*)d_in[17];
  float* out = (float*)d_out;

  __half *crossh, *difh, *hw1, *hw2, *hw3, *hw4, *hw5, *hw6;
  cudaGetSymbolAddress((void**)&crossh, g_crossh);
  cudaGetSymbolAddress((void**)&difh,   g_difh);
  cudaGetSymbolAddress((void**)&hw1,    g_hw1);
  cudaGetSymbolAddress((void**)&hw2,    g_hw2);
  cudaGetSymbolAddress((void**)&hw3,    g_hw3);
  cudaGetSymbolAddress((void**)&hw4,    g_hw4);
  cudaGetSymbolAddress((void**)&hw5,    g_hw5);
  cudaGetSymbolAddress((void**)&hw6,    g_hw6);

  prep_kernel<<<1, 32>>>(pair, temp);

  CvtArgs ca;
  ca.src[0] = cm_w1; ca.dst[0] = hw1;
  ca.src[1] = cm_w2; ca.dst[1] = hw2;
  ca.src[2] = df_w1; ca.dst[2] = hw3;
  ca.src[3] = df_w2; ca.dst[3] = hw4;
  ca.src[4] = fu_w1; ca.dst[4] = hw5;
  ca.src[5] = fu_w2; ca.dst[5] = hw6;
  ca.cum[0] = 0;
  ca.cum[1] = 49152;
  ca.cum[2] = 65536;
  ca.cum[3] = 98304;
  ca.cum[4] = 114688;
  ca.cum[5] = 212992;
  ca.cum[6] = 245760;
  cvt_all<<<(245760 + 255) / 256, 256>>>(ca);

  const size_t SM_AB = 77824;    // 2 CTAs/SM
  const size_t SM_C  = 218112;   // 1 CTA/SM

  { auto k = fused14;
    cudaFuncSetAttribute(k, cudaFuncAttributeMaxDynamicSharedMemorySize, (int)SM_AB);
    k<<<T_TOK / 64, 256, SM_AB>>>(str, sca, hw1, cm_b1, hw2, cm_b2,
                                  hw3, df_b1, hw4, df_b2, crossh, difh); }
  { auto k = fused56;
    cudaFuncSetAttribute(k, cudaFuncAttributeMaxDynamicSharedMemorySize, (int)SM_C);
    k<<<T_TOK / 64, 512, SM_C>>>(crossh, difh, str, sca, hw5, fu_b1, hw6, fu_b2,
                                 lng, lnb, out); }
}